// round 15
// baseline (speedup 1.0000x reference)
#include <cuda_runtime.h>
#include <cuda_bf16.h>
#include <math.h>

#define BATCH  16
#define SEQ    512
#define DMODEL 768
#define NHEAD  12
#define DHEAD  64
#define NDIST  32

// ---------------- scratch (static device memory; referenced by symbol only) ----------------
__device__ float g_x  [BATCH*SEQ*DMODEL];
__device__ float g_q  [BATCH*SEQ*DMODEL];   // layout (B,H,N,DK)
__device__ float g_k  [BATCH*SEQ*DMODEL];   // layout (B,H,N,DK)
__device__ float g_v  [BATCH*SEQ*DMODEL];   // layout (B,H,N,DK)
__device__ float g_ctx[BATCH*SEQ*DMODEL];   // layout (B,N,H*DK)
__device__ int   g_px [BATCH*SEQ];
__device__ int   g_py [BATCH*SEQ];

// ---------------- LayerNorm ----------------
__global__ __launch_bounds__(256) void ln_kernel(
    const float* __restrict__ feat,
    const float* __restrict__ gamma,
    const float* __restrict__ beta)
{
    int row = blockIdx.x;
    const float* x = feat + (size_t)row * DMODEL;
    float* y = g_x + (size_t)row * DMODEL;
    int t = threadIdx.x;

    float v0 = x[t], v1 = x[t + 256], v2 = x[t + 512];
    float s  = v0 + v1 + v2;
    float q  = v0*v0 + v1*v1 + v2*v2;

    __shared__ float ss[8], sq[8];
    #pragma unroll
    for (int o = 16; o > 0; o >>= 1) {
        s += __shfl_xor_sync(0xffffffffu, s, o);
        q += __shfl_xor_sync(0xffffffffu, q, o);
    }
    if ((t & 31) == 0) { ss[t >> 5] = s; sq[t >> 5] = q; }
    __syncthreads();
    if (t == 0) {
        float a = 0.f, b2 = 0.f;
        #pragma unroll
        for (int i = 0; i < 8; i++) { a += ss[i]; b2 += sq[i]; }
        ss[0] = a; sq[0] = b2;
    }
    __syncthreads();
    float mean = ss[0] * (1.0f / DMODEL);
    float var  = sq[0] * (1.0f / DMODEL) - mean * mean;
    float inv  = rsqrtf(var + 1e-5f);

    y[t]       = (v0 - mean) * inv * gamma[t]       + beta[t];
    y[t + 256] = (v1 - mean) * inv * gamma[t + 256] + beta[t + 256];
    y[t + 512] = (v2 - mean) * inv * gamma[t + 512] + beta[t + 512];
}

// ---------------- patch bins (exact replica of reference semantics) ----------------
__global__ void bins_kernel(
    const float* __restrict__ boxes,
    const int* __restrict__ image_sizes)
{
    int idx = blockIdx.x * blockDim.x + threadIdx.x;
    if (idx >= BATCH * SEQ) return;
    int b = idx / SEQ;
    float w = (float)image_sizes[b * 4 + 0];
    float h = (float)image_sizes[b * 4 + 1];
    const float* bx = boxes + (size_t)idx * 4;
    float x0 = bx[0] * w, y0 = bx[1] * h, x1 = bx[2] * w, y1 = bx[3] * h;
    float spaw = floorf(w / 11.0f);
    float spah = floorf(h / 11.0f);
    float cx = floorf((x0 + x1) / 2.0f);
    float cy = floorf((y0 + y1) / 2.0f);
    int pxv = 0, pyv = 0;
    for (int j = 10; j >= 0; j--) {
        float lbw = (float)j * spaw, hbw = (float)(j + 1) * spaw;
        if (lbw <= cx && cx <= hbw) pxv = j;
        float lbh = (float)j * spah, hbh = (float)(j + 1) * spah;
        if (lbh <= cy && cy <= hbh) pyv = j;
    }
    g_px[idx] = pxv;
    g_py[idx] = pyv;
}

// ---------------- bf16 3x helpers ----------------
__device__ __forceinline__ void bf16_split(float v, __nv_bfloat16& h, __nv_bfloat16& l)
{
    h = __float2bfloat16_rn(v);
    l = __float2bfloat16_rn(v - __bfloat162float(h));
}

__device__ __forceinline__ unsigned bf16pack(__nv_bfloat16 a, __nv_bfloat16 b)
{
    __nv_bfloat162 p = __halves2bfloat162(a, b);   // .x (low) = even-k
    return *reinterpret_cast<unsigned*>(&p);
}

__device__ __forceinline__ void split2(float f0, float f1, unsigned& hi, unsigned& lo)
{
    __nv_bfloat16 h0,l0,h1,l1;
    bf16_split(f0, h0, l0); bf16_split(f1, h1, l1);
    hi = bf16pack(h0, h1); lo = bf16pack(l0, l1);
}

template<int STR>
__device__ __forceinline__ void store_row_bf16(
    unsigned (*Hi)[STR], unsigned (*Lo)[STR], int kp0, int m, float4 v)
{
    unsigned h01, l01, h23, l23;
    split2(v.x, v.y, h01, l01);
    split2(v.z, v.w, h23, l23);
    Hi[kp0    ][m] = h01; Lo[kp0    ][m] = l01;
    Hi[kp0 + 1][m] = h23; Lo[kp0 + 1][m] = l23;
}

#define MMA_BF16(D, A, B0, B1)                                                   \
    asm volatile("mma.sync.aligned.m16n8k16.row.col.f32.bf16.bf16.f32 "          \
                 "{%0,%1,%2,%3},{%4,%5,%6,%7},{%8,%9},{%0,%1,%2,%3};"            \
                 : "+f"(D[0]), "+f"(D[1]), "+f"(D[2]), "+f"(D[3])                \
                 : "r"(A[0]), "r"(A[1]), "r"(A[2]), "r"(A[3]), "r"(B0), "r"(B1))

// ---------------- shared GEMM body (3xBF16, NT, 128x128 tile) ----------------
template<int SCATTER>
__device__ __forceinline__ void gemm_body(
    const float* __restrict__ A, const float* __restrict__ W,
    const float* __restrict__ bias, float* __restrict__ Cdst,
    int row0, int col0)
{
    const int K = DMODEL;
    __shared__ unsigned As_hi[2][8][136], As_lo[2][8][136];
    __shared__ unsigned Ws_hi[2][8][136], Ws_lo[2][8][136];

    const int t    = threadIdx.x;
    const int lane = t & 31;
    const int wid  = t >> 5;
    const int warp_m = wid & 3;
    const int warp_n = wid >> 2;
    const int r = lane >> 2;
    const int c = lane & 3;

    const int fm = t >> 2;
    const int kq = (t & 3) * 4;
    const int kp0 = (t & 3) * 2;

    const float* Ap = A + (size_t)(row0 + fm) * K + kq;
    const float* Wp = W + (size_t)(col0 + fm) * K + kq;

    float d[2][8][4];
    #pragma unroll
    for (int i = 0; i < 2; i++)
        #pragma unroll
        for (int j = 0; j < 8; j++)
            #pragma unroll
            for (int e = 0; e < 4; e++) d[i][j][e] = 0.f;

    float4 aR0 = *(const float4*)(Ap);
    float4 aR1 = *(const float4*)(Ap + (size_t)64 * K);
    float4 wR0 = *(const float4*)(Wp);
    float4 wR1 = *(const float4*)(Wp + (size_t)64 * K);

    store_row_bf16<136>(As_hi[0], As_lo[0], kp0, fm,      aR0);
    store_row_bf16<136>(As_hi[0], As_lo[0], kp0, fm + 64, aR1);
    store_row_bf16<136>(Ws_hi[0], Ws_lo[0], kp0, fm,      wR0);
    store_row_bf16<136>(Ws_hi[0], Ws_lo[0], kp0, fm + 64, wR1);
    __syncthreads();

    const int NIT = K / 16;
    for (int it = 0; it < NIT; it++) {
        const int buf = it & 1;
        if (it + 1 < NIT) {
            int k0 = (it + 1) * 16;
            aR0 = *(const float4*)(Ap + k0);
            aR1 = *(const float4*)(Ap + (size_t)64 * K + k0);
            wR0 = *(const float4*)(Wp + k0);
            wR1 = *(const float4*)(Wp + (size_t)64 * K + k0);
        }
        {
            unsigned (*Ah)[136] = As_hi[buf];
            unsigned (*Al)[136] = As_lo[buf];
            unsigned (*Wh)[136] = Ws_hi[buf];
            unsigned (*Wl)[136] = Ws_lo[buf];

            unsigned ah[2][4], al[2][4];
            #pragma unroll
            for (int mt = 0; mt < 2; mt++) {
                int rb = warp_m * 32 + mt * 16 + r;
                ah[mt][0] = Ah[c][rb];     ah[mt][1] = Ah[c][rb + 8];
                ah[mt][2] = Ah[c + 4][rb]; ah[mt][3] = Ah[c + 4][rb + 8];
                al[mt][0] = Al[c][rb];     al[mt][1] = Al[c][rb + 8];
                al[mt][2] = Al[c + 4][rb]; al[mt][3] = Al[c + 4][rb + 8];
            }
            #pragma unroll
            for (int nt = 0; nt < 8; nt++) {
                int nb = warp_n * 64 + nt * 8 + r;
                unsigned b0h = Wh[c][nb], b1h = Wh[c + 4][nb];
                unsigned b0l = Wl[c][nb], b1l = Wl[c + 4][nb];
                #pragma unroll
                for (int mt = 0; mt < 2; mt++) {
                    MMA_BF16(d[mt][nt], ah[mt], b0h, b1h);
                    MMA_BF16(d[mt][nt], ah[mt], b0l, b1l);
                    MMA_BF16(d[mt][nt], al[mt], b0h, b1h);
                }
            }
        }
        if (it + 1 < NIT) {
            int nb = buf ^ 1;
            store_row_bf16<136>(As_hi[nb], As_lo[nb], kp0, fm,      aR0);
            store_row_bf16<136>(As_hi[nb], As_lo[nb], kp0, fm + 64, aR1);
            store_row_bf16<136>(Ws_hi[nb], Ws_lo[nb], kp0, fm,      wR0);
            store_row_bf16<136>(Ws_hi[nb], Ws_lo[nb], kp0, fm + 64, wR1);
        }
        __syncthreads();
    }

    #pragma unroll
    for (int mt = 0; mt < 2; mt++) {
        int m0 = row0 + warp_m * 32 + mt * 16 + r;
        #pragma unroll
        for (int nt = 0; nt < 8; nt++) {
            int n = col0 + warp_n * 64 + nt * 8 + 2 * c;
            float b0v = bias[n], b1v = bias[n + 1];
            float v00 = d[mt][nt][0] + b0v, v01 = d[mt][nt][1] + b1v;
            float v10 = d[mt][nt][2] + b0v, v11 = d[mt][nt][3] + b1v;
            if (SCATTER == 0) {
                *(float2*)&Cdst[(size_t)m0 * DMODEL + n]       = make_float2(v00, v01);
                *(float2*)&Cdst[(size_t)(m0 + 8) * DMODEL + n] = make_float2(v10, v11);
            } else {
                int hh = n >> 6, dk = n & 63;
                int b1_ = m0 >> 9,       nq1 = m0 & 511;
                int b2_ = (m0 + 8) >> 9, nq2 = (m0 + 8) & 511;
                *(float2*)&Cdst[(((size_t)(b1_ * NHEAD + hh)) * SEQ + nq1) * DHEAD + dk] = make_float2(v00, v01);
                *(float2*)&Cdst[(((size_t)(b2_ * NHEAD + hh)) * SEQ + nq2) * DHEAD + dk] = make_float2(v10, v11);
            }
        }
    }
}

__global__ __launch_bounds__(256) void gemm_qkv(
    const float* __restrict__ Wq, const float* __restrict__ Wk, const float* __restrict__ Wv,
    const float* __restrict__ bq, const float* __restrict__ bk, const float* __restrict__ bv)
{
    const float* W    = (blockIdx.z == 0) ? Wq : (blockIdx.z == 1) ? Wk : Wv;
    const float* bias = (blockIdx.z == 0) ? bq : (blockIdx.z == 1) ? bk : bv;
    float* Cdst       = (blockIdx.z == 0) ? g_q : (blockIdx.z == 1) ? g_k : g_v;
    gemm_body<1>(g_x, W, bias, Cdst, blockIdx.y * 128, blockIdx.x * 128);
}

__global__ __launch_bounds__(256) void gemm_out(
    const float* __restrict__ Wo, const float* __restrict__ bo, float* __restrict__ out)
{
    gemm_body<0>(g_ctx, Wo, bo, out, blockIdx.y * 128, blockIdx.x * 128);
}

// ---------------- fused attention ----------------
// grid (q-tile=16 x 32 rows, bh=192), 512 threads = 16 warps.
// Phase 1: warp_m(2) x warp_n(8). Phase 3: warp_m(2) x warp_n(4) x warp_ks(2) with
// k-partial accumulation and a one-time smem reduction (buffer aliased over Q region).
#define SSTR     516
#define SM_S     0                                      // 32*516*4 = 66048 B
#define SM_QHI   66048                                  // unsigned Qhi[32][40]  5120 B (also red buf)
#define SM_QLO   71168                                  // unsigned Qlo[32][40]  5120 B (also red buf)
#define SM_KHI   76288                                  // unsigned Khi[32][72]  9216 B (also Vhi)
#define SM_KLO   85504                                  // unsigned Klo[32][72]  9216 B (also Vlo)
#define SM_EMB   94720                                  // float emb[32]          128 B
#define SM_PXQ   94848                                  // int spxq[32]           128 B
#define SM_PYQ   94976                                  // int spyq[32]           128 B
#define SM_PXK   95104                                  // int spxk[512]         2048 B
#define SM_PYK   97152                                  // int spyk[512]         2048 B
#define SMEM_ATTN 99200

__global__ __launch_bounds__(512, 2) void fused_attn(
    const float* __restrict__ dist_emb, float* __restrict__ att)
{
    extern __shared__ char smraw[];
    float    (*S)[SSTR]  = (float(*)[SSTR])   (smraw + SM_S);
    unsigned (*Su)[SSTR] = (unsigned(*)[SSTR])(smraw + SM_S);
    unsigned (*Qhi)[40]  = (unsigned(*)[40])(smraw + SM_QHI);
    unsigned (*Qlo)[40]  = (unsigned(*)[40])(smraw + SM_QLO);
    unsigned (*Khi)[72]  = (unsigned(*)[72])(smraw + SM_KHI);
    unsigned (*Klo)[72]  = (unsigned(*)[72])(smraw + SM_KLO);
    float*   emb  = (float*)(smraw + SM_EMB);
    int*     spxq = (int*)  (smraw + SM_PXQ);
    int*     spyq = (int*)  (smraw + SM_PYQ);
    int*     spxk = (int*)  (smraw + SM_PXK);
    int*     spyk = (int*)  (smraw + SM_PYK);

    const int t    = threadIdx.x;
    const int lane = t & 31;
    const int wid  = t >> 5;          // 0..15
    const int warp_m = wid & 1;       // rows warp_m*16 + {r, r+8}
    const int warp_n = wid >> 1;      // phase 1: 0..7 -> 8 cols each
    const int r = lane >> 2;          // 0..7
    const int c = lane & 3;           // 0..3

    const int bh = blockIdx.y;
    const int b  = bh / NHEAD, h = bh % NHEAD;
    const int q0 = blockIdx.x * 32;

    const float* Qb = g_q + (size_t)bh * SEQ * DHEAD;
    const float* Kb = g_k + (size_t)bh * SEQ * DHEAD;
    const float* Vb = g_v + (size_t)bh * SEQ * DHEAD;

    // ---- preload tables + Q tile ----
    if (t < NDIST) emb[t] = dist_emb[t * NHEAD + h];
    if (t < 32) {
        spxq[t] = g_px[b * SEQ + q0 + t];
        spyq[t] = g_py[b * SEQ + q0 + t];
    }
    spxk[t] = g_px[b * SEQ + t];
    spyk[t] = g_py[b * SEQ + t];

    // Q fill: 32 rows x 64 dim, one float4 per thread
    {
        int frw = t >> 4;             // 0..31
        int fc  = (t & 15) * 4;       // 0..60
        float4 v = *(const float4*)(Qb + (size_t)(q0 + frw) * DHEAD + fc);
        store_row_bf16<40>(Qhi, Qlo, (t & 15) * 2, frw, v);
    }
    __syncthreads();

    // ---- Q fragments (registers, reused 8x) ----
    const int rb = warp_m * 16 + r;
    unsigned qah[4][4], qal[4][4];
    #pragma unroll
    for (int ks = 0; ks < 4; ks++) {
        qah[ks][0] = Qhi[ks * 8 + c][rb];     qah[ks][1] = Qhi[ks * 8 + c][rb + 8];
        qah[ks][2] = Qhi[ks * 8 + c + 4][rb]; qah[ks][3] = Qhi[ks * 8 + c + 4][rb + 8];
        qal[ks][0] = Qlo[ks * 8 + c][rb];     qal[ks][1] = Qlo[ks * 8 + c][rb + 8];
        qal[ks][2] = Qlo[ks * 8 + c + 4][rb]; qal[ks][3] = Qlo[ks * 8 + c + 4][rb + 8];
    }

    const int frow = t >> 3;          // 0..63 (K/V fill rows)
    const int fcq  = (t & 7) * 8;
    const int fkp0 = (t & 7) * 4;

    // ---- phase 1: S = QK^T/8 + bias ----
    for (int kt = 0; kt < 8; kt++) {
        float4 kv[2];
        {
            const float* kp = Kb + (size_t)(kt * 64 + frow) * DHEAD + fcq;
            #pragma unroll
            for (int u = 0; u < 2; u++) kv[u] = *(const float4*)(kp + u * 4);
        }
        __syncthreads();
        #pragma unroll
        for (int u = 0; u < 2; u++)
            store_row_bf16<72>(Khi, Klo, fkp0 + u * 2, frow, kv[u]);
        __syncthreads();

        float d[4];
        d[0] = d[1] = d[2] = d[3] = 0.f;

        #pragma unroll
        for (int ks = 0; ks < 4; ks++) {
            int nb = warp_n * 8 + r;
            unsigned b0h = Khi[ks * 8 + c][nb], b1h = Khi[ks * 8 + c + 4][nb];
            unsigned b0l = Klo[ks * 8 + c][nb], b1l = Klo[ks * 8 + c + 4][nb];
            MMA_BF16(d, qah[ks], b0h, b1h);
            MMA_BF16(d, qah[ks], b0l, b1l);
            MMA_BF16(d, qal[ks], b0h, b1h);
        }

        int pxq0 = spxq[rb],     pyq0 = spyq[rb];
        int pxq1 = spxq[rb + 8], pyq1 = spyq[rb + 8];
        {
            int ncol = warp_n * 8 + 2 * c;
            int kg   = kt * 64 + ncol;
            int pxk0 = spxk[kg],     pyk0 = spyk[kg];
            int pxk1 = spxk[kg + 1], pyk1 = spyk[kg + 1];
            int dx00 = pxk0 - pxq0, dy00 = pyk0 - pyq0;
            int dx01 = pxk1 - pxq0, dy01 = pyk1 - pyq0;
            int dx10 = pxk0 - pxq1, dy10 = pyk0 - pyq1;
            int dx11 = pxk1 - pxq1, dy11 = pyk1 - pyq1;
            float e00 = emb[(int)(sqrtf((float)(dx00*dx00 + dy00*dy00)) * 2.0f)];
            float e01 = emb[(int)(sqrtf((float)(dx01*dx01 + dy01*dy01)) * 2.0f)];
            float e10 = emb[(int)(sqrtf((float)(dx10*dx10 + dy10*dy10)) * 2.0f)];
            float e11 = emb[(int)(sqrtf((float)(dx11*dx11 + dy11*dy11)) * 2.0f)];
            S[rb][kg]         = d[0] * 0.125f + e00;
            S[rb][kg + 1]     = d[1] * 0.125f + e01;
            S[rb + 8][kg]     = d[2] * 0.125f + e10;
            S[rb + 8][kg + 1] = d[3] * 0.125f + e11;
        }
    }
    __syncthreads();

    // ---- phase 2: softmax (warp x 2 rows), write att, repack row to bf16 hi/lo in place ----
    for (int rr = 0; rr < 2; rr++) {
        int row = wid * 2 + rr;
        float* Sr = S[row];
        float4 x0 = ((float4*)Sr)[lane];
        float4 x1 = ((float4*)Sr)[lane + 32];
        float4 x2 = ((float4*)Sr)[lane + 64];
        float4 x3 = ((float4*)Sr)[lane + 96];
        float m = fmaxf(fmaxf(fmaxf(x0.x,x0.y),fmaxf(x0.z,x0.w)),
                  fmaxf(fmaxf(fmaxf(x1.x,x1.y),fmaxf(x1.z,x1.w)),
                  fmaxf(fmaxf(fmaxf(x2.x,x2.y),fmaxf(x2.z,x2.w)),
                        fmaxf(fmaxf(x3.x,x3.y),fmaxf(x3.z,x3.w)))));
        #pragma unroll
        for (int o = 16; o > 0; o >>= 1) m = fmaxf(m, __shfl_xor_sync(0xffffffffu, m, o));
        x0.x = __expf(x0.x - m); x0.y = __expf(x0.y - m); x0.z = __expf(x0.z - m); x0.w = __expf(x0.w - m);
        x1.x = __expf(x1.x - m); x1.y = __expf(x1.y - m); x1.z = __expf(x1.z - m); x1.w = __expf(x1.w - m);
        x2.x = __expf(x2.x - m); x2.y = __expf(x2.y - m); x2.z = __expf(x2.z - m); x2.w = __expf(x2.w - m);
        x3.x = __expf(x3.x - m); x3.y = __expf(x3.y - m); x3.z = __expf(x3.z - m); x3.w = __expf(x3.w - m);
        float s = (x0.x+x0.y+x0.z+x0.w) + (x1.x+x1.y+x1.z+x1.w)
                + (x2.x+x2.y+x2.z+x2.w) + (x3.x+x3.y+x3.z+x3.w);
        #pragma unroll
        for (int o = 16; o > 0; o >>= 1) s += __shfl_xor_sync(0xffffffffu, s, o);
        float inv = 1.0f / s;
        x0.x*=inv; x0.y*=inv; x0.z*=inv; x0.w*=inv;
        x1.x*=inv; x1.y*=inv; x1.z*=inv; x1.w*=inv;
        x2.x*=inv; x2.y*=inv; x2.z*=inv; x2.w*=inv;
        x3.x*=inv; x3.y*=inv; x3.z*=inv; x3.w*=inv;

        float* ar = att + ((size_t)bh * SEQ + q0 + row) * SEQ;
        ((float4*)ar)[lane]      = x0;
        ((float4*)ar)[lane + 32] = x1;
        ((float4*)ar)[lane + 64] = x2;
        ((float4*)ar)[lane + 96] = x3;

        // repack in place: hi words [0..255], lo words [258..513]
        unsigned* Sru = (unsigned*)Sr;
        uint2 wh, wl;
        split2(x0.x, x0.y, wh.x, wl.x); split2(x0.z, x0.w, wh.y, wl.y);
        *(uint2*)&Sru[lane * 2]            = wh;
        *(uint2*)&Sru[258 + lane * 2]      = wl;
        split2(x1.x, x1.y, wh.x, wl.x); split2(x1.z, x1.w, wh.y, wl.y);
        *(uint2*)&Sru[64 + lane * 2]       = wh;
        *(uint2*)&Sru[258 + 64 + lane * 2] = wl;
        split2(x2.x, x2.y, wh.x, wl.x); split2(x2.z, x2.w, wh.y, wl.y);
        *(uint2*)&Sru[128 + lane * 2]      = wh;
        *(uint2*)&Sru[258 + 128 + lane * 2]= wl;
        split2(x3.x, x3.y, wh.x, wl.x); split2(x3.z, x3.w, wh.y, wl.y);
        *(uint2*)&Sru[192 + lane * 2]      = wh;
        *(uint2*)&Sru[258 + 192 + lane * 2]= wl;
    }
    __syncthreads();

    // ---- phase 3: ctx = P @ V, k-split across warp halves ----
    unsigned (*Vhi)[72] = Khi;
    unsigned (*Vlo)[72] = Klo;
    const int wn3 = (wid >> 1) & 3;   // 0..3 -> 16 cols each
    const int wks = wid >> 3;         // 0..1 -> ks half
    float ctx[2][4];
    #pragma unroll
    for (int nt = 0; nt < 2; nt++)
        #pragma unroll
        for (int e = 0; e < 4; e++) ctx[nt][e] = 0.f;

    const int vkp = t >> 4;           // 0..31 (key pair within tile)
    const int vd0 = (t & 15) * 4;     // 0..60

    for (int kt = 0; kt < 8; kt++) {
        float4 v0, v1;
        {
            const float* vp = Vb + (size_t)(kt * 64 + 2 * vkp) * DHEAD + vd0;
            v0 = *(const float4*)(vp);
            v1 = *(const float4*)(vp + DHEAD);
        }
        __syncthreads();
        {
            unsigned hi, lo;
            split2(v0.x, v1.x, hi, lo); Vhi[vkp][vd0]     = hi; Vlo[vkp][vd0]     = lo;
            split2(v0.y, v1.y, hi, lo); Vhi[vkp][vd0 + 1] = hi; Vlo[vkp][vd0 + 1] = lo;
            split2(v0.z, v1.z, hi, lo); Vhi[vkp][vd0 + 2] = hi; Vlo[vkp][vd0 + 2] = lo;
            split2(v0.w, v1.w, hi, lo); Vhi[vkp][vd0 + 3] = hi; Vlo[vkp][vd0 + 3] = lo;
        }
        __syncthreads();

        #pragma unroll
        for (int ksi = 0; ksi < 2; ksi++) {
            int ks  = wks * 2 + ksi;
            int kbp = kt * 32 + ks * 8;
            unsigned ah[4], al[4];
            ah[0] = Su[rb][kbp + c];           ah[1] = Su[rb + 8][kbp + c];
            ah[2] = Su[rb][kbp + c + 4];       ah[3] = Su[rb + 8][kbp + c + 4];
            al[0] = Su[rb][258 + kbp + c];     al[1] = Su[rb + 8][258 + kbp + c];
            al[2] = Su[rb][258 + kbp + c + 4]; al[3] = Su[rb + 8][258 + kbp + c + 4];
            #pragma unroll
            for (int nt = 0; nt < 2; nt++) {
                int nb = wn3 * 16 + nt * 8 + r;
                unsigned b0h = Vhi[ks * 8 + c][nb], b1h = Vhi[ks * 8 + c + 4][nb];
                unsigned b0l = Vlo[ks * 8 + c][nb], b1l = Vlo[ks * 8 + c + 4][nb];
                MMA_BF16(ctx[nt], ah, b0h, b1h);
                MMA_BF16(ctx[nt], ah, b0l, b1l);
                MMA_BF16(ctx[nt], al, b0h, b1h);
            }
        }
    }

    // ---- cross-half reduction (buffer aliased over dead Q region) + epilogue ----
    float (*red)[68] = (float(*)[68])(smraw + SM_QHI);   // 32*68*4 = 8704 B <= 10240 B
    __syncthreads();
    if (wks == 1) {
        #pragma unroll
        for (int nt = 0; nt < 2; nt++) {
            int col = wn3 * 16 + nt * 8 + 2 * c;
            *(float2*)&red[rb][col]     = make_float2(ctx[nt][0], ctx[nt][1]);
            *(float2*)&red[rb + 8][col] = make_float2(ctx[nt][2], ctx[nt][3]);
        }
    }
    __syncthreads();
    if (wks == 0) {
        #pragma unroll
        for (int nt = 0; nt < 2; nt++) {
            int col = wn3 * 16 + nt * 8 + 2 * c;
            float2 p0 = *(float2*)&red[rb][col];
            float2 p1 = *(float2*)&red[rb + 8][col];
            int q1 = q0 + rb;
            *(float2*)&g_ctx[((size_t)(b * SEQ + q1)) * DMODEL + h * DHEAD + col] =
                make_float2(ctx[nt][0] + p0.x, ctx[nt][1] + p0.y);
            *(float2*)&g_ctx[((size_t)(b * SEQ + q1 + 8)) * DMODEL + h * DHEAD + col] =
                make_float2(ctx[nt][2] + p1.x, ctx[nt][3] + p1.y);
        }
    }
}

// ---------------- launch ----------------
extern "C" void kernel_launch(void* const* d_in, const int* in_sizes, int n_in,
                              void* d_out, int out_size)
{
    const float* features    = (const float*)d_in[0];
    const float* boxes       = (const float*)d_in[1];
    const int*   image_sizes = (const int*)  d_in[2];
    const float* Wq    = (const float*)d_in[3];
    const float* bq    = (const float*)d_in[4];
    const float* Wk    = (const float*)d_in[5];
    const float* bk    = (const float*)d_in[6];
    const float* Wv    = (const float*)d_in[7];
    const float* bv    = (const float*)d_in[8];
    const float* Wo    = (const float*)d_in[9];
    const float* bo    = (const float*)d_in[10];
    const float* gamma = (const float*)d_in[11];
    const float* beta  = (const float*)d_in[12];
    const float* demb  = (const float*)d_in[13];

    float* out = (float*)d_out;
    float* att = out + (size_t)BATCH * SEQ * DMODEL;

    cudaFuncSetAttribute(fused_attn, cudaFuncAttributeMaxDynamicSharedMemorySize, SMEM_ATTN);

    const int M = BATCH * SEQ;   // 8192

    ln_kernel<<<M, 256>>>(features, gamma, beta);
    bins_kernel<<<(M + 255) / 256, 256>>>(boxes, image_sizes);

    gemm_qkv<<<dim3(DMODEL / 128, M / 128, 3), 256>>>(Wq, Wk, Wv, bq, bk, bv);

    fused_attn<<<dim3(SEQ / 32, BATCH * NHEAD), 512, SMEM_ATTN>>>(demb, att);

    gemm_out<<<dim3(DMODEL / 128, M / 128), 256>>>(Wo, bo, out);
}

// round 16
// speedup vs baseline: 1.0775x; 1.0775x over previous
#include <cuda_runtime.h>
#include <cuda_bf16.h>
#include <math.h>

#define BATCH  16
#define SEQ    512
#define DMODEL 768
#define NHEAD  12
#define DHEAD  64
#define NDIST  32

// ---------------- scratch (static device memory; referenced by symbol only) ----------------
__device__ float g_x  [BATCH*SEQ*DMODEL];
__device__ float g_q  [BATCH*SEQ*DMODEL];   // layout (B,H,N,DK)
__device__ float g_k  [BATCH*SEQ*DMODEL];   // layout (B,H,N,DK)
__device__ float g_v  [BATCH*SEQ*DMODEL];   // layout (B,H,N,DK)
__device__ float g_ctx[BATCH*SEQ*DMODEL];   // layout (B,N,H*DK)
__device__ int   g_px [BATCH*SEQ];
__device__ int   g_py [BATCH*SEQ];

// ---------------- LayerNorm ----------------
__global__ __launch_bounds__(256) void ln_kernel(
    const float* __restrict__ feat,
    const float* __restrict__ gamma,
    const float* __restrict__ beta)
{
    int row = blockIdx.x;
    const float* x = feat + (size_t)row * DMODEL;
    float* y = g_x + (size_t)row * DMODEL;
    int t = threadIdx.x;

    float v0 = x[t], v1 = x[t + 256], v2 = x[t + 512];
    float s  = v0 + v1 + v2;
    float q  = v0*v0 + v1*v1 + v2*v2;

    __shared__ float ss[8], sq[8];
    #pragma unroll
    for (int o = 16; o > 0; o >>= 1) {
        s += __shfl_xor_sync(0xffffffffu, s, o);
        q += __shfl_xor_sync(0xffffffffu, q, o);
    }
    if ((t & 31) == 0) { ss[t >> 5] = s; sq[t >> 5] = q; }
    __syncthreads();
    if (t == 0) {
        float a = 0.f, b2 = 0.f;
        #pragma unroll
        for (int i = 0; i < 8; i++) { a += ss[i]; b2 += sq[i]; }
        ss[0] = a; sq[0] = b2;
    }
    __syncthreads();
    float mean = ss[0] * (1.0f / DMODEL);
    float var  = sq[0] * (1.0f / DMODEL) - mean * mean;
    float inv  = rsqrtf(var + 1e-5f);

    y[t]       = (v0 - mean) * inv * gamma[t]       + beta[t];
    y[t + 256] = (v1 - mean) * inv * gamma[t + 256] + beta[t + 256];
    y[t + 512] = (v2 - mean) * inv * gamma[t + 512] + beta[t + 512];
}

// ---------------- patch bins (exact replica of reference semantics) ----------------
__global__ void bins_kernel(
    const float* __restrict__ boxes,
    const int* __restrict__ image_sizes)
{
    int idx = blockIdx.x * blockDim.x + threadIdx.x;
    if (idx >= BATCH * SEQ) return;
    int b = idx / SEQ;
    float w = (float)image_sizes[b * 4 + 0];
    float h = (float)image_sizes[b * 4 + 1];
    const float* bx = boxes + (size_t)idx * 4;
    float x0 = bx[0] * w, y0 = bx[1] * h, x1 = bx[2] * w, y1 = bx[3] * h;
    float spaw = floorf(w / 11.0f);
    float spah = floorf(h / 11.0f);
    float cx = floorf((x0 + x1) / 2.0f);
    float cy = floorf((y0 + y1) / 2.0f);
    int pxv = 0, pyv = 0;
    for (int j = 10; j >= 0; j--) {
        float lbw = (float)j * spaw, hbw = (float)(j + 1) * spaw;
        if (lbw <= cx && cx <= hbw) pxv = j;
        float lbh = (float)j * spah, hbh = (float)(j + 1) * spah;
        if (lbh <= cy && cy <= hbh) pyv = j;
    }
    g_px[idx] = pxv;
    g_py[idx] = pyv;
}

// ---------------- bf16 3x helpers ----------------
__device__ __forceinline__ void bf16_split(float v, __nv_bfloat16& h, __nv_bfloat16& l)
{
    h = __float2bfloat16_rn(v);
    l = __float2bfloat16_rn(v - __bfloat162float(h));
}

__device__ __forceinline__ unsigned bf16pack(__nv_bfloat16 a, __nv_bfloat16 b)
{
    __nv_bfloat162 p = __halves2bfloat162(a, b);   // .x (low) = even-k
    return *reinterpret_cast<unsigned*>(&p);
}

__device__ __forceinline__ void split2(float f0, float f1, unsigned& hi, unsigned& lo)
{
    __nv_bfloat16 h0,l0,h1,l1;
    bf16_split(f0, h0, l0); bf16_split(f1, h1, l1);
    hi = bf16pack(h0, h1); lo = bf16pack(l0, l1);
}

template<int STR>
__device__ __forceinline__ void store_row_bf16(
    unsigned (*Hi)[STR], unsigned (*Lo)[STR], int kp0, int m, float4 v)
{
    unsigned h01, l01, h23, l23;
    split2(v.x, v.y, h01, l01);
    split2(v.z, v.w, h23, l23);
    Hi[kp0    ][m] = h01; Lo[kp0    ][m] = l01;
    Hi[kp0 + 1][m] = h23; Lo[kp0 + 1][m] = l23;
}

#define MMA_BF16(D, A, B0, B1)                                                   \
    asm volatile("mma.sync.aligned.m16n8k16.row.col.f32.bf16.bf16.f32 "          \
                 "{%0,%1,%2,%3},{%4,%5,%6,%7},{%8,%9},{%0,%1,%2,%3};"            \
                 : "+f"(D[0]), "+f"(D[1]), "+f"(D[2]), "+f"(D[3])                \
                 : "r"(A[0]), "r"(A[1]), "r"(A[2]), "r"(A[3]), "r"(B0), "r"(B1))

#define LDSM_X4(R0, R1, R2, R3, ADDR)                                            \
    asm volatile("ldmatrix.sync.aligned.m8n8.x4.shared.b16 {%0,%1,%2,%3}, [%4];" \
                 : "=r"(R0), "=r"(R1), "=r"(R2), "=r"(R3) : "r"(ADDR))

// ---------------- shared GEMM body (3xBF16, NT, 128x128 tile) ----------------
template<int SCATTER>
__device__ __forceinline__ void gemm_body(
    const float* __restrict__ A, const float* __restrict__ W,
    const float* __restrict__ bias, float* __restrict__ Cdst,
    int row0, int col0)
{
    const int K = DMODEL;
    __shared__ unsigned As_hi[2][8][136], As_lo[2][8][136];
    __shared__ unsigned Ws_hi[2][8][136], Ws_lo[2][8][136];

    const int t    = threadIdx.x;
    const int lane = t & 31;
    const int wid  = t >> 5;
    const int warp_m = wid & 3;
    const int warp_n = wid >> 2;
    const int r = lane >> 2;
    const int c = lane & 3;

    const int fm = t >> 2;
    const int kq = (t & 3) * 4;
    const int kp0 = (t & 3) * 2;

    const float* Ap = A + (size_t)(row0 + fm) * K + kq;
    const float* Wp = W + (size_t)(col0 + fm) * K + kq;

    float d[2][8][4];
    #pragma unroll
    for (int i = 0; i < 2; i++)
        #pragma unroll
        for (int j = 0; j < 8; j++)
            #pragma unroll
            for (int e = 0; e < 4; e++) d[i][j][e] = 0.f;

    float4 aR0 = *(const float4*)(Ap);
    float4 aR1 = *(const float4*)(Ap + (size_t)64 * K);
    float4 wR0 = *(const float4*)(Wp);
    float4 wR1 = *(const float4*)(Wp + (size_t)64 * K);

    store_row_bf16<136>(As_hi[0], As_lo[0], kp0, fm,      aR0);
    store_row_bf16<136>(As_hi[0], As_lo[0], kp0, fm + 64, aR1);
    store_row_bf16<136>(Ws_hi[0], Ws_lo[0], kp0, fm,      wR0);
    store_row_bf16<136>(Ws_hi[0], Ws_lo[0], kp0, fm + 64, wR1);
    __syncthreads();

    const int NIT = K / 16;
    for (int it = 0; it < NIT; it++) {
        const int buf = it & 1;
        if (it + 1 < NIT) {
            int k0 = (it + 1) * 16;
            aR0 = *(const float4*)(Ap + k0);
            aR1 = *(const float4*)(Ap + (size_t)64 * K + k0);
            wR0 = *(const float4*)(Wp + k0);
            wR1 = *(const float4*)(Wp + (size_t)64 * K + k0);
        }
        {
            unsigned (*Ah)[136] = As_hi[buf];
            unsigned (*Al)[136] = As_lo[buf];
            unsigned (*Wh)[136] = Ws_hi[buf];
            unsigned (*Wl)[136] = Ws_lo[buf];

            unsigned ah[2][4], al[2][4];
            #pragma unroll
            for (int mt = 0; mt < 2; mt++) {
                int rb = warp_m * 32 + mt * 16 + r;
                ah[mt][0] = Ah[c][rb];     ah[mt][1] = Ah[c][rb + 8];
                ah[mt][2] = Ah[c + 4][rb]; ah[mt][3] = Ah[c + 4][rb + 8];
                al[mt][0] = Al[c][rb];     al[mt][1] = Al[c][rb + 8];
                al[mt][2] = Al[c + 4][rb]; al[mt][3] = Al[c + 4][rb + 8];
            }
            #pragma unroll
            for (int nt = 0; nt < 8; nt++) {
                int nb = warp_n * 64 + nt * 8 + r;
                unsigned b0h = Wh[c][nb], b1h = Wh[c + 4][nb];
                unsigned b0l = Wl[c][nb], b1l = Wl[c + 4][nb];
                #pragma unroll
                for (int mt = 0; mt < 2; mt++) {
                    MMA_BF16(d[mt][nt], ah[mt], b0h, b1h);
                    MMA_BF16(d[mt][nt], ah[mt], b0l, b1l);
                    MMA_BF16(d[mt][nt], al[mt], b0h, b1h);
                }
            }
        }
        if (it + 1 < NIT) {
            int nb = buf ^ 1;
            store_row_bf16<136>(As_hi[nb], As_lo[nb], kp0, fm,      aR0);
            store_row_bf16<136>(As_hi[nb], As_lo[nb], kp0, fm + 64, aR1);
            store_row_bf16<136>(Ws_hi[nb], Ws_lo[nb], kp0, fm,      wR0);
            store_row_bf16<136>(Ws_hi[nb], Ws_lo[nb], kp0, fm + 64, wR1);
        }
        __syncthreads();
    }

    #pragma unroll
    for (int mt = 0; mt < 2; mt++) {
        int m0 = row0 + warp_m * 32 + mt * 16 + r;
        #pragma unroll
        for (int nt = 0; nt < 8; nt++) {
            int n = col0 + warp_n * 64 + nt * 8 + 2 * c;
            float b0v = bias[n], b1v = bias[n + 1];
            float v00 = d[mt][nt][0] + b0v, v01 = d[mt][nt][1] + b1v;
            float v10 = d[mt][nt][2] + b0v, v11 = d[mt][nt][3] + b1v;
            if (SCATTER == 0) {
                *(float2*)&Cdst[(size_t)m0 * DMODEL + n]       = make_float2(v00, v01);
                *(float2*)&Cdst[(size_t)(m0 + 8) * DMODEL + n] = make_float2(v10, v11);
            } else {
                int hh = n >> 6, dk = n & 63;
                int b1_ = m0 >> 9,       nq1 = m0 & 511;
                int b2_ = (m0 + 8) >> 9, nq2 = (m0 + 8) & 511;
                *(float2*)&Cdst[(((size_t)(b1_ * NHEAD + hh)) * SEQ + nq1) * DHEAD + dk] = make_float2(v00, v01);
                *(float2*)&Cdst[(((size_t)(b2_ * NHEAD + hh)) * SEQ + nq2) * DHEAD + dk] = make_float2(v10, v11);
            }
        }
    }
}

__global__ __launch_bounds__(256) void gemm_qkv(
    const float* __restrict__ Wq, const float* __restrict__ Wk, const float* __restrict__ Wv,
    const float* __restrict__ bq, const float* __restrict__ bk, const float* __restrict__ bv)
{
    const float* W    = (blockIdx.z == 0) ? Wq : (blockIdx.z == 1) ? Wk : Wv;
    const float* bias = (blockIdx.z == 0) ? bq : (blockIdx.z == 1) ? bk : bv;
    float* Cdst       = (blockIdx.z == 0) ? g_q : (blockIdx.z == 1) ? g_k : g_v;
    gemm_body<1>(g_x, W, bias, Cdst, blockIdx.y * 128, blockIdx.x * 128);
}

__global__ __launch_bounds__(256) void gemm_out(
    const float* __restrict__ Wo, const float* __restrict__ bo, float* __restrict__ out)
{
    gemm_body<0>(g_ctx, Wo, bo, out, blockIdx.y * 128, blockIdx.x * 128);
}

// ---------------- fused attention (LDSM fragment loads) ----------------
// grid (q-tile=16 x 32 rows, bh=192), 512 threads = 16 warps (warp_m 0..1, warp_n 0..7).
// K/V tiles stored TRANSPOSED [n][kpair] stride 36 for non-trans ldmatrix B loads.
// S rows: fp32 scores, then in-place packed: hi words [0..255], lo words [260..515].
#define SSTR     516
#define SM_S     0                                      // 32*516*4 = 66048 B
#define SM_QHI   66048                                  // unsigned Qhi[32][40]  5120 B
#define SM_QLO   71168                                  // unsigned Qlo[32][40]  5120 B
#define SM_KHI   76288                                  // unsigned Kt_hi[64][36] 9216 B (also Vt_hi)
#define SM_KLO   85504                                  // unsigned Kt_lo[64][36] 9216 B (also Vt_lo)
#define SM_EMB   94720                                  // float emb[32]          128 B
#define SM_PXQ   94848                                  // int spxq[32]           128 B
#define SM_PYQ   94976                                  // int spyq[32]           128 B
#define SM_PXK   95104                                  // int spxk[512]         2048 B
#define SM_PYK   97152                                  // int spyk[512]         2048 B
#define SMEM_ATTN 99200

__global__ __launch_bounds__(512, 2) void fused_attn(
    const float* __restrict__ dist_emb, float* __restrict__ att)
{
    extern __shared__ char smraw[];
    float    (*S)[SSTR]  = (float(*)[SSTR])   (smraw + SM_S);
    unsigned (*Qhi)[40]  = (unsigned(*)[40])(smraw + SM_QHI);
    unsigned (*Qlo)[40]  = (unsigned(*)[40])(smraw + SM_QLO);
    unsigned (*Kt_hi)[36] = (unsigned(*)[36])(smraw + SM_KHI);
    unsigned (*Kt_lo)[36] = (unsigned(*)[36])(smraw + SM_KLO);
    float*   emb  = (float*)(smraw + SM_EMB);
    int*     spxq = (int*)  (smraw + SM_PXQ);
    int*     spyq = (int*)  (smraw + SM_PYQ);
    int*     spxk = (int*)  (smraw + SM_PXK);
    int*     spyk = (int*)  (smraw + SM_PYK);

    const unsigned sb = (unsigned)__cvta_generic_to_shared(smraw);

    const int t    = threadIdx.x;
    const int lane = t & 31;
    const int wid  = t >> 5;          // 0..15
    const int warp_m = wid & 1;       // rows warp_m*16 + {r, r+8}
    const int warp_n = wid >> 1;      // 0..7 -> 8 cols each
    const int r = lane >> 2;          // 0..7
    const int c = lane & 3;           // 0..3

    const int bh = blockIdx.y;
    const int b  = bh / NHEAD, h = bh % NHEAD;
    const int q0 = blockIdx.x * 32;

    const float* Qb = g_q + (size_t)bh * SEQ * DHEAD;
    const float* Kb = g_k + (size_t)bh * SEQ * DHEAD;
    const float* Vb = g_v + (size_t)bh * SEQ * DHEAD;

    // ---- preload tables + Q tile ----
    if (t < NDIST) emb[t] = dist_emb[t * NHEAD + h];
    if (t < 32) {
        spxq[t] = g_px[b * SEQ + q0 + t];
        spyq[t] = g_py[b * SEQ + q0 + t];
    }
    spxk[t] = g_px[b * SEQ + t];
    spyk[t] = g_py[b * SEQ + t];

    // Q fill: 32 rows x 64 dim, one float4 per thread ([kpair][m] layout, stride 40)
    {
        int frw = t >> 4;             // 0..31
        int fc  = (t & 15) * 4;       // 0..60
        float4 v = *(const float4*)(Qb + (size_t)(q0 + frw) * DHEAD + fc);
        store_row_bf16<40>(Qhi, Qlo, (t & 15) * 2, frw, v);
    }
    __syncthreads();

    // ---- Q fragments (registers, reused 8x) ----
    const int rb = warp_m * 16 + r;
    unsigned qah[4][4], qal[4][4];
    #pragma unroll
    for (int ks = 0; ks < 4; ks++) {
        qah[ks][0] = Qhi[ks * 8 + c][rb];     qah[ks][1] = Qhi[ks * 8 + c][rb + 8];
        qah[ks][2] = Qhi[ks * 8 + c + 4][rb]; qah[ks][3] = Qhi[ks * 8 + c + 4][rb + 8];
        qal[ks][0] = Qlo[ks * 8 + c][rb];     qal[ks][1] = Qlo[ks * 8 + c][rb + 8];
        qal[ks][2] = Qlo[ks * 8 + c + 4][rb]; qal[ks][3] = Qlo[ks * 8 + c + 4][rb + 8];
    }

    // fill mapping for K (transposed store): row = key, cols = dim kpairs
    const int frow = t >> 3;          // 0..63 (key)
    const int fcq  = (t & 7) * 8;     // dim base
    const int fkp0 = (t & 7) * 4;     // kpair base

    // per-lane ldmatrix address for K/V B-tiles (rows = n, tiles j over kpair quads)
    const unsigned brow = warp_n * 8 + (lane & 7);
    const unsigned btile = (lane >> 3) & 3;                 // 0..3
    const unsigned kvb_hi = sb + SM_KHI + ((brow * 36 + btile * 4) << 2);
    const unsigned kvb_lo = sb + SM_KLO + ((brow * 36 + btile * 4) << 2);

    // ---- phase 1: S = QK^T/8 + bias ----
    for (int kt = 0; kt < 8; kt++) {
        float4 kv[2];
        {
            const float* kp = Kb + (size_t)(kt * 64 + frow) * DHEAD + fcq;
            kv[0] = *(const float4*)(kp);
            kv[1] = *(const float4*)(kp + 4);
        }
        __syncthreads();
        {
            unsigned hh[4], ll[4];
            split2(kv[0].x, kv[0].y, hh[0], ll[0]);
            split2(kv[0].z, kv[0].w, hh[1], ll[1]);
            split2(kv[1].x, kv[1].y, hh[2], ll[2]);
            split2(kv[1].z, kv[1].w, hh[3], ll[3]);
            *(uint4*)&Kt_hi[frow][fkp0] = make_uint4(hh[0], hh[1], hh[2], hh[3]);
            *(uint4*)&Kt_lo[frow][fkp0] = make_uint4(ll[0], ll[1], ll[2], ll[3]);
        }
        __syncthreads();

        float d[4];
        d[0] = d[1] = d[2] = d[3] = 0.f;

        #pragma unroll
        for (int p = 0; p < 2; p++) {       // ks pair (2p, 2p+1)
            unsigned bh0, bh1, bh2, bh3, bl0, bl1, bl2, bl3;
            LDSM_X4(bh0, bh1, bh2, bh3, kvb_hi + p * 64);
            LDSM_X4(bl0, bl1, bl2, bl3, kvb_lo + p * 64);
            MMA_BF16(d, qah[2*p],     bh0, bh1);
            MMA_BF16(d, qah[2*p],     bl0, bl1);
            MMA_BF16(d, qal[2*p],     bh0, bh1);
            MMA_BF16(d, qah[2*p + 1], bh2, bh3);
            MMA_BF16(d, qah[2*p + 1], bl2, bl3);
            MMA_BF16(d, qal[2*p + 1], bh2, bh3);
        }

        int pxq0 = spxq[rb],     pyq0 = spyq[rb];
        int pxq1 = spxq[rb + 8], pyq1 = spyq[rb + 8];
        {
            int ncol = warp_n * 8 + 2 * c;
            int kg   = kt * 64 + ncol;
            int pxk0 = spxk[kg],     pyk0 = spyk[kg];
            int pxk1 = spxk[kg + 1], pyk1 = spyk[kg + 1];
            int dx00 = pxk0 - pxq0, dy00 = pyk0 - pyq0;
            int dx01 = pxk1 - pxq0, dy01 = pyk1 - pyq0;
            int dx10 = pxk0 - pxq1, dy10 = pyk0 - pyq1;
            int dx11 = pxk1 - pxq1, dy11 = pyk1 - pyq1;
            float e00 = emb[(int)(sqrtf((float)(dx00*dx00 + dy00*dy00)) * 2.0f)];
            float e01 = emb[(int)(sqrtf((float)(dx01*dx01 + dy01*dy01)) * 2.0f)];
            float e10 = emb[(int)(sqrtf((float)(dx10*dx10 + dy10*dy10)) * 2.0f)];
            float e11 = emb[(int)(sqrtf((float)(dx11*dx11 + dy11*dy11)) * 2.0f)];
            *(float2*)&S[rb][kg]     = make_float2(d[0] * 0.125f + e00, d[1] * 0.125f + e01);
            *(float2*)&S[rb + 8][kg] = make_float2(d[2] * 0.125f + e10, d[3] * 0.125f + e11);
        }
    }
    __syncthreads();

    // ---- phase 2: softmax (warp x 2 rows), write att, repack row to bf16 hi/lo in place ----
    for (int rr = 0; rr < 2; rr++) {
        int row = wid * 2 + rr;
        float* Sr = S[row];
        float4 x0 = ((float4*)Sr)[lane];
        float4 x1 = ((float4*)Sr)[lane + 32];
        float4 x2 = ((float4*)Sr)[lane + 64];
        float4 x3 = ((float4*)Sr)[lane + 96];
        float m = fmaxf(fmaxf(fmaxf(x0.x,x0.y),fmaxf(x0.z,x0.w)),
                  fmaxf(fmaxf(fmaxf(x1.x,x1.y),fmaxf(x1.z,x1.w)),
                  fmaxf(fmaxf(fmaxf(x2.x,x2.y),fmaxf(x2.z,x2.w)),
                        fmaxf(fmaxf(x3.x,x3.y),fmaxf(x3.z,x3.w)))));
        #pragma unroll
        for (int o = 16; o > 0; o >>= 1) m = fmaxf(m, __shfl_xor_sync(0xffffffffu, m, o));
        x0.x = __expf(x0.x - m); x0.y = __expf(x0.y - m); x0.z = __expf(x0.z - m); x0.w = __expf(x0.w - m);
        x1.x = __expf(x1.x - m); x1.y = __expf(x1.y - m); x1.z = __expf(x1.z - m); x1.w = __expf(x1.w - m);
        x2.x = __expf(x2.x - m); x2.y = __expf(x2.y - m); x2.z = __expf(x2.z - m); x2.w = __expf(x2.w - m);
        x3.x = __expf(x3.x - m); x3.y = __expf(x3.y - m); x3.z = __expf(x3.z - m); x3.w = __expf(x3.w - m);
        float s = (x0.x+x0.y+x0.z+x0.w) + (x1.x+x1.y+x1.z+x1.w)
                + (x2.x+x2.y+x2.z+x2.w) + (x3.x+x3.y+x3.z+x3.w);
        #pragma unroll
        for (int o = 16; o > 0; o >>= 1) s += __shfl_xor_sync(0xffffffffu, s, o);
        float inv = 1.0f / s;
        x0.x*=inv; x0.y*=inv; x0.z*=inv; x0.w*=inv;
        x1.x*=inv; x1.y*=inv; x1.z*=inv; x1.w*=inv;
        x2.x*=inv; x2.y*=inv; x2.z*=inv; x2.w*=inv;
        x3.x*=inv; x3.y*=inv; x3.z*=inv; x3.w*=inv;

        float* ar = att + ((size_t)bh * SEQ + q0 + row) * SEQ;
        ((float4*)ar)[lane]      = x0;
        ((float4*)ar)[lane + 32] = x1;
        ((float4*)ar)[lane + 64] = x2;
        ((float4*)ar)[lane + 96] = x3;

        // repack in place: hi words [0..255], lo words [260..515]
        unsigned* Sru = (unsigned*)Sr;
        uint2 wh, wl;
        split2(x0.x, x0.y, wh.x, wl.x); split2(x0.z, x0.w, wh.y, wl.y);
        *(uint2*)&Sru[lane * 2]            = wh;
        *(uint2*)&Sru[260 + lane * 2]      = wl;
        split2(x1.x, x1.y, wh.x, wl.x); split2(x1.z, x1.w, wh.y, wl.y);
        *(uint2*)&Sru[64 + lane * 2]       = wh;
        *(uint2*)&Sru[260 + 64 + lane * 2] = wl;
        split2(x2.x, x2.y, wh.x, wl.x); split2(x2.z, x2.w, wh.y, wl.y);
        *(uint2*)&Sru[128 + lane * 2]      = wh;
        *(uint2*)&Sru[260 + 128 + lane * 2]= wl;
        split2(x3.x, x3.y, wh.x, wl.x); split2(x3.z, x3.w, wh.y, wl.y);
        *(uint2*)&Sru[192 + lane * 2]      = wh;
        *(uint2*)&Sru[260 + 192 + lane * 2]= wl;
    }
    __syncthreads();

    // ---- phase 3: ctx = P @ V (LDSM for A and B) ----
    unsigned (*Vt_hi)[36] = Kt_hi;     // reuse, now [d][keypair]
    unsigned (*Vt_lo)[36] = Kt_lo;
    float ctx[4];
    ctx[0] = ctx[1] = ctx[2] = ctx[3] = 0.f;

    const int vkp = t >> 4;           // 0..31 (key pair within tile)
    const int vd0 = (t & 15) * 4;     // 0..60

    // per-lane A-fragment ldmatrix base addresses (S panel)
    const unsigned arow = warp_m * 16 + (lane & 7) + ((lane >> 3) & 1) * 8;
    const unsigned acolw = ((lane >> 4) & 1) * 4;
    const unsigned sa_hi = sb + SM_S + ((arow * SSTR + acolw) << 2);
    const unsigned sa_lo = sa_hi + 260 * 4;

    for (int kt = 0; kt < 8; kt++) {
        float4 v0, v1;
        {
            const float* vp = Vb + (size_t)(kt * 64 + 2 * vkp) * DHEAD + vd0;
            v0 = *(const float4*)(vp);
            v1 = *(const float4*)(vp + DHEAD);
        }
        __syncthreads();
        {
            unsigned hi, lo;
            split2(v0.x, v1.x, hi, lo); Vt_hi[vd0][vkp]     = hi; Vt_lo[vd0][vkp]     = lo;
            split2(v0.y, v1.y, hi, lo); Vt_hi[vd0 + 1][vkp] = hi; Vt_lo[vd0 + 1][vkp] = lo;
            split2(v0.z, v1.z, hi, lo); Vt_hi[vd0 + 2][vkp] = hi; Vt_lo[vd0 + 2][vkp] = lo;
            split2(v0.w, v1.w, hi, lo); Vt_hi[vd0 + 3][vkp] = hi; Vt_lo[vd0 + 3][vkp] = lo;
        }
        __syncthreads();

        #pragma unroll
        for (int p = 0; p < 2; p++) {       // ks pair (2p, 2p+1)
            unsigned bh0, bh1, bh2, bh3, bl0, bl1, bl2, bl3;
            LDSM_X4(bh0, bh1, bh2, bh3, kvb_hi + p * 64);
            LDSM_X4(bl0, bl1, bl2, bl3, kvb_lo + p * 64);
            #pragma unroll
            for (int ksl = 0; ksl < 2; ksl++) {
                int ks = 2 * p + ksl;
                unsigned ah[4], al[4];
                unsigned off = (unsigned)(kt * 32 + ks * 8) << 2;
                LDSM_X4(ah[0], ah[1], ah[2], ah[3], sa_hi + off);
                LDSM_X4(al[0], al[1], al[2], al[3], sa_lo + off);
                unsigned vb0h = ksl ? bh2 : bh0, vb1h = ksl ? bh3 : bh1;
                unsigned vb0l = ksl ? bl2 : bl0, vb1l = ksl ? bl3 : bl1;
                MMA_BF16(ctx, ah, vb0h, vb1h);
                MMA_BF16(ctx, ah, vb0l, vb1l);
                MMA_BF16(ctx, al, vb0h, vb1h);
            }
        }
    }

    // ---- epilogue ----
    {
        int q1 = q0 + rb;
        int dcol = warp_n * 8 + 2 * c;
        *(float2*)&g_ctx[((size_t)(b * SEQ + q1)) * DMODEL + h * DHEAD + dcol] =
            make_float2(ctx[0], ctx[1]);
        *(float2*)&g_ctx[((size_t)(b * SEQ + q1 + 8)) * DMODEL + h * DHEAD + dcol] =
            make_float2(ctx[2], ctx[3]);
    }
}

// ---------------- launch ----------------
extern "C" void kernel_launch(void* const* d_in, const int* in_sizes, int n_in,
                              void* d_out, int out_size)
{
    const float* features    = (const float*)d_in[0];
    const float* boxes       = (const float*)d_in[1];
    const int*   image_sizes = (const int*)  d_in[2];
    const float* Wq    = (const float*)d_in[3];
    const float* bq    = (const float*)d_in[4];
    const float* Wk    = (const float*)d_in[5];
    const float* bk    = (const float*)d_in[6];
    const float* Wv    = (const float*)d_in[7];
    const float* bv    = (const float*)d_in[8];
    const float* Wo    = (const float*)d_in[9];
    const float* bo    = (const float*)d_in[10];
    const float* gamma = (const float*)d_in[11];
    const float* beta  = (const float*)d_in[12];
    const float* demb  = (const float*)d_in[13];

    float* out = (float*)d_out;
    float* att = out + (size_t)BATCH * SEQ * DMODEL;

    cudaFuncSetAttribute(fused_attn, cudaFuncAttributeMaxDynamicSharedMemorySize, SMEM_ATTN);

    const int M = BATCH * SEQ;   // 8192

    ln_kernel<<<M, 256>>>(features, gamma, beta);
    bins_kernel<<<(M + 255) / 256, 256>>>(boxes, image_sizes);

    gemm_qkv<<<dim3(DMODEL / 128, M / 128, 3), 256>>>(Wq, Wk, Wv, bq, bk, bv);

    fused_attn<<<dim3(SEQ / 32, BATCH * NHEAD), 512, SMEM_ATTN>>>(demb, att);

    gemm_out<<<dim3(DMODEL / 128, M / 128), 256>>>(Wo, bo, out);
}